// round 7
// baseline (speedup 1.0000x reference)
#include <cuda_runtime.h>
#include <cuda_bf16.h>

#define NREF  4096
#define NIN   8192
#define DFEAT 512
#define PDIM  256
#define LDS   40          // 32 + 8 pad (bf16 elems) -> 80B row stride

#define TILE_ELEMS (128 * LDS)
#define TILE_BYTES (TILE_ELEMS * 2)       // 10240
#define STAGE_BYTES (4 * TILE_BYTES)      // 40960: Ah, Al, Bh, Bl
#define SMEM_TOTAL (2 * STAGE_BYTES + 512)

// GEMM2 (64x128 tile) smem layout
#define G2_AT   (64 * LDS * 2)            // 5120
#define G2_BT   TILE_BYTES                // 10240
#define G2_STAGE (2 * G2_AT + 2 * G2_BT)  // 30720
#define G2_SMEM  (2 * G2_STAGE)           // 61440

// ---------------- scratch (device globals: allocation-guard safe) ----------
__device__ __nv_bfloat16 g_Xh[NREF * DFEAT];
__device__ __nv_bfloat16 g_Xl[NREF * DFEAT];
__device__ __nv_bfloat16 g_Dh[NIN * DFEAT];
__device__ __nv_bfloat16 g_Dl[NIN * DFEAT];
__device__ __nv_bfloat16 g_Ah[PDIM * NREF];
__device__ __nv_bfloat16 g_Al[PDIM * NREF];
__device__ __nv_bfloat16 g_Kth[(size_t)NIN * NREF];   // K^T hi  [NIN, NREF]
__device__ __nv_bfloat16 g_Ktl[(size_t)NIN * NREF];   // K^T lo

__device__ __forceinline__ unsigned sm32(const void* p) {
    unsigned r;
    asm("{.reg .u64 t; cvta.to.shared.u64 t, %1; cvt.u32.u64 %0, t;}" : "=r"(r) : "l"(p));
    return r;
}

// Load one 128x32 bf16 tile (row-major source, row stride K elems) via cp.async.
__device__ __forceinline__ void load_tile(unsigned sbuf, const __nv_bfloat16* src,
                                          int rowBase, int K, int kOff, int tid) {
    const int row = tid >> 1;
    const char* g = (const char*)(src + (size_t)(rowBase + row) * K + kOff + (tid & 1) * 16);
    const unsigned s = sbuf + row * (LDS * 2) + (tid & 1) * 32;
    asm volatile("cp.async.cg.shared.global [%0], [%1], 16;\n\t"
                 "cp.async.cg.shared.global [%2], [%3], 16;"
                 :: "r"(s), "l"(g), "r"(s + 16), "l"(g + 16));
}

// Load one 64x32 bf16 tile with the first 128 threads.
__device__ __forceinline__ void load_tile64(unsigned sbuf, const __nv_bfloat16* src,
                                            int rowBase, int K, int kOff, int tid) {
    if (tid < 128) {
        const int row = tid >> 1;
        const char* g = (const char*)(src + (size_t)(rowBase + row) * K + kOff + (tid & 1) * 16);
        const unsigned s = sbuf + row * (LDS * 2) + (tid & 1) * 32;
        asm volatile("cp.async.cg.shared.global [%0], [%1], 16;\n\t"
                     "cp.async.cg.shared.global [%2], [%3], 16;"
                     :: "r"(s), "l"(g), "r"(s + 16), "l"(g + 16));
    }
}

__device__ __forceinline__ void mma16(float* c, const unsigned* a, unsigned b0, unsigned b1) {
    asm volatile(
        "mma.sync.aligned.m16n8k16.row.col.f32.bf16.bf16.f32 "
        "{%0,%1,%2,%3}, {%4,%5,%6,%7}, {%8,%9}, {%0,%1,%2,%3};"
        : "+f"(c[0]), "+f"(c[1]), "+f"(c[2]), "+f"(c[3])
        : "r"(a[0]), "r"(a[1]), "r"(a[2]), "r"(a[3]), "r"(b0), "r"(b1));
}

#define LDSM4(r, addr)                                                           \
    asm volatile("ldmatrix.sync.aligned.m8n8.x4.shared.b16 {%0,%1,%2,%3}, [%4];" \
                 : "=r"((r)[0]), "=r"((r)[1]), "=r"((r)[2]), "=r"((r)[3])        \
                 : "r"(addr))

// One BLK_K=32 stage (32x64 warp tile), fused 3-term split accumulation:
//   c += Ah.Bh + Ah.Bl + Al.Bh  (terms outermost: accumulator reuse distance 4)
__device__ __forceinline__ void compute3_k32(unsigned sAh, unsigned sAl,
                                             unsigned sBh, unsigned sBl,
                                             int warpM, int warpN, int lane,
                                             float (*c)[8][4]) {
#pragma unroll
    for (int kk = 0; kk < 32; kk += 16) {
        const unsigned aoff = ((warpM * 32 + (lane & 15)) * LDS + kk + (lane >> 4) * 8) * 2;
        unsigned ah[2][4], al[2][4];
        LDSM4(ah[0], sAh + aoff);
        LDSM4(ah[1], sAh + aoff + 16 * LDS * 2);
        LDSM4(al[0], sAl + aoff);
        LDSM4(al[1], sAl + aoff + 16 * LDS * 2);
#pragma unroll
        for (int g = 0; g < 4; g++) {
            const unsigned boff = ((warpN * 64 + g * 16 + (lane & 7) + ((lane >> 4) & 1) * 8) * LDS
                                   + kk + ((lane >> 3) & 1) * 8) * 2;
            unsigned bh[4], bl[4];
            LDSM4(bh, sBh + boff);
            LDSM4(bl, sBl + boff);
            mma16(c[0][2 * g],     ah[0], bh[0], bh[1]);
            mma16(c[0][2 * g + 1], ah[0], bh[2], bh[3]);
            mma16(c[1][2 * g],     ah[1], bh[0], bh[1]);
            mma16(c[1][2 * g + 1], ah[1], bh[2], bh[3]);
            mma16(c[0][2 * g],     ah[0], bl[0], bl[1]);
            mma16(c[0][2 * g + 1], ah[0], bl[2], bl[3]);
            mma16(c[1][2 * g],     ah[1], bl[0], bl[1]);
            mma16(c[1][2 * g + 1], ah[1], bl[2], bl[3]);
            mma16(c[0][2 * g],     al[0], bh[0], bh[1]);
            mma16(c[0][2 * g + 1], al[0], bh[2], bh[3]);
            mma16(c[1][2 * g],     al[1], bh[0], bh[1]);
            mma16(c[1][2 * g + 1], al[1], bh[2], bh[3]);
        }
    }
}

// ---------------------------------------------------------------------------
// GEMM1 (transposed): Kt[j,i] = mask(Z[j]==Z_ref[i]) * (desc[j].X_ref[i])^expK
// 256 threads / CTA, 8 warps, warp grid 4x2 of 32x64 tiles.
// ---------------------------------------------------------------------------
__global__ __launch_bounds__(256, 2) void gemm1_mma(const int* __restrict__ Zq,
                                                    const int* __restrict__ Zx,
                                                    const int* __restrict__ expKp) {
    extern __shared__ char dynsm[];
    const int tid = threadIdx.x, lane = tid & 31, wid = tid >> 5;
    const int warpM = wid & 3, warpN = wid >> 2;
    const int jBase = blockIdx.y * 128, iBase = blockIdx.x * 128;

    int* Zcol = (int*)(dynsm + 2 * STAGE_BYTES);
    if (tid < 128) Zcol[tid] = Zx[iBase + tid];

    float c[2][8][4];
#pragma unroll
    for (int i = 0; i < 2; i++)
#pragma unroll
        for (int j = 0; j < 8; j++)
#pragma unroll
            for (int k = 0; k < 4; k++) c[i][j][k] = 0.0f;

    unsigned st[2][4];
#pragma unroll
    for (int s = 0; s < 2; s++)
#pragma unroll
        for (int t = 0; t < 4; t++)
            st[s][t] = sm32(dynsm + s * STAGE_BYTES + t * TILE_BYTES);

    load_tile(st[0][0], g_Dh, jBase, DFEAT, 0, tid);
    load_tile(st[0][1], g_Dl, jBase, DFEAT, 0, tid);
    load_tile(st[0][2], g_Xh, iBase, DFEAT, 0, tid);
    load_tile(st[0][3], g_Xl, iBase, DFEAT, 0, tid);
    asm volatile("cp.async.commit_group;" ::: "memory");

    const int NITER = DFEAT / 32;       // 16
    for (int it = 0; it < NITER; it++) {
        const int b = it & 1;
        if (it + 1 < NITER) {
            const int kOff = (it + 1) * 32;
            load_tile(st[1 - b][0], g_Dh, jBase, DFEAT, kOff, tid);
            load_tile(st[1 - b][1], g_Dl, jBase, DFEAT, kOff, tid);
            load_tile(st[1 - b][2], g_Xh, iBase, DFEAT, kOff, tid);
            load_tile(st[1 - b][3], g_Xl, iBase, DFEAT, kOff, tid);
            asm volatile("cp.async.commit_group;" ::: "memory");
            asm volatile("cp.async.wait_group 1;" ::: "memory");
        } else {
            asm volatile("cp.async.wait_group 0;" ::: "memory");
        }
        __syncthreads();
        compute3_k32(st[b][0], st[b][1], st[b][2], st[b][3], warpM, warpN, lane, c);
        __syncthreads();
    }

    // epilogue: pow, mask, bf16 hi/lo split, store K^T
    const int e = expKp[0];
#pragma unroll
    for (int mi = 0; mi < 2; mi++) {
        const int r0 = jBase + warpM * 32 + mi * 16 + (lane >> 2);
        const int zr0 = Zq[r0], zr1 = Zq[r0 + 8];
        const size_t ro0 = (size_t)r0 * NREF, ro1 = (size_t)(r0 + 8) * NREF;
#pragma unroll
        for (int ni = 0; ni < 8; ni++) {
            const int colL = warpN * 64 + ni * 8 + 2 * (lane & 3);
            const int zc0 = Zcol[colL], zc1 = Zcol[colL + 1];
            float v0 = c[mi][ni][0], v1 = c[mi][ni][1];
            float v2 = c[mi][ni][2], v3 = c[mi][ni][3];
            float p0 = 1.f, p1 = 1.f, p2 = 1.f, p3 = 1.f;
            for (int t = 0; t < e; t++) { p0 *= v0; p1 *= v1; p2 *= v2; p3 *= v3; }
            if (zr0 != zc0) p0 = 0.f;
            if (zr0 != zc1) p1 = 0.f;
            if (zr1 != zc0) p2 = 0.f;
            if (zr1 != zc1) p3 = 0.f;

            __nv_bfloat16 h0 = __float2bfloat16(p0), h1 = __float2bfloat16(p1);
            __nv_bfloat16 h2 = __float2bfloat16(p2), h3 = __float2bfloat16(p3);
            __nv_bfloat162 hh01, hh23, ll01, ll23;
            hh01.x = h0; hh01.y = h1;
            hh23.x = h2; hh23.y = h3;
            ll01.x = __float2bfloat16(p0 - __bfloat162float(h0));
            ll01.y = __float2bfloat16(p1 - __bfloat162float(h1));
            ll23.x = __float2bfloat16(p2 - __bfloat162float(h2));
            ll23.y = __float2bfloat16(p3 - __bfloat162float(h3));

            const size_t cg = (size_t)iBase + colL;
            *(__nv_bfloat162*)(g_Kth + ro0 + cg) = hh01;
            *(__nv_bfloat162*)(g_Kth + ro1 + cg) = hh23;
            *(__nv_bfloat162*)(g_Ktl + ro0 + cg) = ll01;
            *(__nv_bfloat162*)(g_Ktl + ro1 + cg) = ll23;
        }
    }
}

// ---------------------------------------------------------------------------
// GEMM2: Y[p,j] = Alpha[p] . Kt[j]
// Retiled 64(M) x 128(N): grid (64, 4) = 256 CTAs -> full 2-CTA/SM wave.
// 8 warps as 2(M) x 4(N), warp tile 32x32.
// ---------------------------------------------------------------------------
__global__ __launch_bounds__(256, 2) void gemm2_mma(float* __restrict__ Y) {
    extern __shared__ char dynsm[];
    const int tid = threadIdx.x, lane = tid & 31, wid = tid >> 5;
    const int warpM = wid & 1, warpN = wid >> 1;
    const int pBase = blockIdx.y * 64, jBase = blockIdx.x * 128;

    float c[2][4][4];
#pragma unroll
    for (int i = 0; i < 2; i++)
#pragma unroll
        for (int j = 0; j < 4; j++)
#pragma unroll
            for (int k = 0; k < 4; k++) c[i][j][k] = 0.0f;

    // stage layout: Ah(5120) Al(5120) Bh(10240) Bl(10240)
    unsigned sAh[2], sAl[2], sBh[2], sBl[2];
#pragma unroll
    for (int s = 0; s < 2; s++) {
        sAh[s] = sm32(dynsm + s * G2_STAGE);
        sAl[s] = sm32(dynsm + s * G2_STAGE + G2_AT);
        sBh[s] = sm32(dynsm + s * G2_STAGE + 2 * G2_AT);
        sBl[s] = sm32(dynsm + s * G2_STAGE + 2 * G2_AT + G2_BT);
    }

    load_tile64(sAh[0], g_Ah, pBase, NREF, 0, tid);
    load_tile64(sAl[0], g_Al, pBase, NREF, 0, tid);
    load_tile(sBh[0], g_Kth, jBase, NREF, 0, tid);
    load_tile(sBl[0], g_Ktl, jBase, NREF, 0, tid);
    asm volatile("cp.async.commit_group;" ::: "memory");

    const int NITER = NREF / 32;        // 128
    for (int it = 0; it < NITER; it++) {
        const int b = it & 1;
        if (it + 1 < NITER) {
            const int kOff = (it + 1) * 32;
            load_tile64(sAh[1 - b], g_Ah, pBase, NREF, kOff, tid);
            load_tile64(sAl[1 - b], g_Al, pBase, NREF, kOff, tid);
            load_tile(sBh[1 - b], g_Kth, jBase, NREF, kOff, tid);
            load_tile(sBl[1 - b], g_Ktl, jBase, NREF, kOff, tid);
            asm volatile("cp.async.commit_group;" ::: "memory");
            asm volatile("cp.async.wait_group 1;" ::: "memory");
        } else {
            asm volatile("cp.async.wait_group 0;" ::: "memory");
        }
        __syncthreads();

        // compute: 32x32 warp tile, 3-term fused
#pragma unroll
        for (int kk = 0; kk < 32; kk += 16) {
            const unsigned aoff = ((warpM * 32 + (lane & 15)) * LDS + kk + (lane >> 4) * 8) * 2;
            unsigned ah[2][4], al[2][4];
            LDSM4(ah[0], sAh[b] + aoff);
            LDSM4(ah[1], sAh[b] + aoff + 16 * LDS * 2);
            LDSM4(al[0], sAl[b] + aoff);
            LDSM4(al[1], sAl[b] + aoff + 16 * LDS * 2);
#pragma unroll
            for (int g = 0; g < 2; g++) {
                const unsigned boff =
                    ((warpN * 32 + g * 16 + (lane & 7) + ((lane >> 4) & 1) * 8) * LDS
                     + kk + ((lane >> 3) & 1) * 8) * 2;
                unsigned bh[4], bl[4];
                LDSM4(bh, sBh[b] + boff);
                LDSM4(bl, sBl[b] + boff);
                mma16(c[0][2 * g],     ah[0], bh[0], bh[1]);
                mma16(c[0][2 * g + 1], ah[0], bh[2], bh[3]);
                mma16(c[1][2 * g],     ah[1], bh[0], bh[1]);
                mma16(c[1][2 * g + 1], ah[1], bh[2], bh[3]);
                mma16(c[0][2 * g],     ah[0], bl[0], bl[1]);
                mma16(c[0][2 * g + 1], ah[0], bl[2], bl[3]);
                mma16(c[1][2 * g],     ah[1], bl[0], bl[1]);
                mma16(c[1][2 * g + 1], ah[1], bl[2], bl[3]);
                mma16(c[0][2 * g],     al[0], bh[0], bh[1]);
                mma16(c[0][2 * g + 1], al[0], bh[2], bh[3]);
                mma16(c[1][2 * g],     al[1], bh[0], bh[1]);
                mma16(c[1][2 * g + 1], al[1], bh[2], bh[3]);
            }
        }
        __syncthreads();
    }

#pragma unroll
    for (int mi = 0; mi < 2; mi++) {
        const int r0 = pBase + warpM * 32 + mi * 16 + (lane >> 2);
        const size_t ro0 = (size_t)r0 * NIN, ro1 = (size_t)(r0 + 8) * NIN;
#pragma unroll
        for (int ni = 0; ni < 4; ni++) {
            const int col = jBase + warpN * 32 + ni * 8 + 2 * (lane & 3);
            *(float2*)(Y + ro0 + col) = make_float2(c[mi][ni][0], c[mi][ni][1]);
            *(float2*)(Y + ro1 + col) = make_float2(c[mi][ni][2], c[mi][ni][3]);
        }
    }
}

// ---------------------------------------------------------------------------
// fp32 -> bf16 hi/lo splits
// ---------------------------------------------------------------------------
__device__ __forceinline__ void split2(float2 v, __nv_bfloat162* hp, __nv_bfloat162* lp, int i) {
    __nv_bfloat16 h0 = __float2bfloat16(v.x), h1 = __float2bfloat16(v.y);
    __nv_bfloat162 hh, ll;
    hh.x = h0; hh.y = h1;
    ll.x = __float2bfloat16(v.x - __bfloat162float(h0));
    ll.y = __float2bfloat16(v.y - __bfloat162float(h1));
    hp[i] = hh; lp[i] = ll;
}
__global__ void split_X(const float* __restrict__ x) {
    int i = blockIdx.x * blockDim.x + threadIdx.x;
    if (i < NREF * DFEAT / 2)
        split2(((const float2*)x)[i], (__nv_bfloat162*)g_Xh, (__nv_bfloat162*)g_Xl, i);
}
__global__ void split_D(const float* __restrict__ x) {
    int i = blockIdx.x * blockDim.x + threadIdx.x;
    if (i < NIN * DFEAT / 2)
        split2(((const float2*)x)[i], (__nv_bfloat162*)g_Dh, (__nv_bfloat162*)g_Dl, i);
}
__global__ void split_A(const float* __restrict__ x) {
    int i = blockIdx.x * blockDim.x + threadIdx.x;
    if (i < PDIM * NREF / 2)
        split2(((const float2*)x)[i], (__nv_bfloat162*)g_Ah, (__nv_bfloat162*)g_Al, i);
}

extern "C" void kernel_launch(void* const* d_in, const int* in_sizes, int n_in,
                              void* d_out, int out_size) {
    const float* Alpha = (const float*)d_in[0];
    const float* X_ref = (const float*)d_in[1];
    const float* desc  = (const float*)d_in[2];
    const int*   Z_ref = (const int*)d_in[3];
    const int*   Z     = (const int*)d_in[4];
    const int*   expK  = (const int*)d_in[5];
    float* Y = (float*)d_out;

    cudaFuncSetAttribute(gemm1_mma, cudaFuncAttributeMaxDynamicSharedMemorySize, SMEM_TOTAL);
    cudaFuncSetAttribute(gemm2_mma, cudaFuncAttributeMaxDynamicSharedMemorySize, G2_SMEM);

    split_X<<<(NREF * DFEAT / 2 + 255) / 256, 256>>>(X_ref);
    split_D<<<(NIN * DFEAT / 2 + 255) / 256, 256>>>(desc);
    split_A<<<(PDIM * NREF / 2 + 255) / 256, 256>>>(Alpha);

    gemm1_mma<<<dim3(NREF / 128, NIN / 128), 256, SMEM_TOTAL>>>(Z, Z_ref, expK);
    gemm2_mma<<<dim3(NIN / 128, PDIM / 64), 256, G2_SMEM>>>(Y);
}

// round 8
// speedup vs baseline: 1.0581x; 1.0581x over previous
#include <cuda_runtime.h>
#include <cuda_bf16.h>

#define NREF  4096
#define NIN   8192
#define DFEAT 512
#define PDIM  256
#define LDS   40          // 32 + 8 pad (bf16 elems) -> 80B row stride

#define TILE_ELEMS (128 * LDS)
#define TILE_BYTES (TILE_ELEMS * 2)       // 10240
#define STAGE_BYTES (4 * TILE_BYTES)      // 40960: Ah, Al, Bh, Bl
#define SMEM_TOTAL (2 * STAGE_BYTES + 512)

// ---------------- scratch (device globals: allocation-guard safe) ----------
__device__ __nv_bfloat16 g_Xh[NREF * DFEAT];
__device__ __nv_bfloat16 g_Xl[NREF * DFEAT];
__device__ __nv_bfloat16 g_Dh[NIN * DFEAT];
__device__ __nv_bfloat16 g_Dl[NIN * DFEAT];
__device__ __nv_bfloat16 g_Ah[PDIM * NREF];
__device__ __nv_bfloat16 g_Al[PDIM * NREF];
__device__ __nv_bfloat16 g_Kth[(size_t)NIN * NREF];   // K^T hi  [NIN, NREF]
__device__ __nv_bfloat16 g_Ktl[(size_t)NIN * NREF];   // K^T lo
__device__ float g_P[2 * PDIM * NIN];                 // split-K partials (16 MB)

__device__ __forceinline__ unsigned sm32(const void* p) {
    unsigned r;
    asm("{.reg .u64 t; cvta.to.shared.u64 t, %1; cvt.u32.u64 %0, t;}" : "=r"(r) : "l"(p));
    return r;
}

// Load one 128x32 bf16 tile (row-major source, row stride K elems) via cp.async.
__device__ __forceinline__ void load_tile(unsigned sbuf, const __nv_bfloat16* src,
                                          int rowBase, int K, int kOff, int tid) {
    const int row = tid >> 1;
    const char* g = (const char*)(src + (size_t)(rowBase + row) * K + kOff + (tid & 1) * 16);
    const unsigned s = sbuf + row * (LDS * 2) + (tid & 1) * 32;
    asm volatile("cp.async.cg.shared.global [%0], [%1], 16;\n\t"
                 "cp.async.cg.shared.global [%2], [%3], 16;"
                 :: "r"(s), "l"(g), "r"(s + 16), "l"(g + 16));
}

__device__ __forceinline__ void mma16(float* c, const unsigned* a, unsigned b0, unsigned b1) {
    asm volatile(
        "mma.sync.aligned.m16n8k16.row.col.f32.bf16.bf16.f32 "
        "{%0,%1,%2,%3}, {%4,%5,%6,%7}, {%8,%9}, {%0,%1,%2,%3};"
        : "+f"(c[0]), "+f"(c[1]), "+f"(c[2]), "+f"(c[3])
        : "r"(a[0]), "r"(a[1]), "r"(a[2]), "r"(a[3]), "r"(b0), "r"(b1));
}

#define LDSM4(r, addr)                                                           \
    asm volatile("ldmatrix.sync.aligned.m8n8.x4.shared.b16 {%0,%1,%2,%3}, [%4];" \
                 : "=r"((r)[0]), "=r"((r)[1]), "=r"((r)[2]), "=r"((r)[3])        \
                 : "r"(addr))

// One BLK_K=32 stage (32x64 warp tile), fused 3-term split accumulation:
//   c += Ah.Bh + Ah.Bl + Al.Bh  (terms outermost: accumulator reuse distance 4)
__device__ __forceinline__ void compute3_k32(unsigned sAh, unsigned sAl,
                                             unsigned sBh, unsigned sBl,
                                             int warpM, int warpN, int lane,
                                             float (*c)[8][4]) {
#pragma unroll
    for (int kk = 0; kk < 32; kk += 16) {
        const unsigned aoff = ((warpM * 32 + (lane & 15)) * LDS + kk + (lane >> 4) * 8) * 2;
        unsigned ah[2][4], al[2][4];
        LDSM4(ah[0], sAh + aoff);
        LDSM4(ah[1], sAh + aoff + 16 * LDS * 2);
        LDSM4(al[0], sAl + aoff);
        LDSM4(al[1], sAl + aoff + 16 * LDS * 2);
#pragma unroll
        for (int g = 0; g < 4; g++) {
            const unsigned boff = ((warpN * 64 + g * 16 + (lane & 7) + ((lane >> 4) & 1) * 8) * LDS
                                   + kk + ((lane >> 3) & 1) * 8) * 2;
            unsigned bh[4], bl[4];
            LDSM4(bh, sBh + boff);
            LDSM4(bl, sBl + boff);
            mma16(c[0][2 * g],     ah[0], bh[0], bh[1]);
            mma16(c[0][2 * g + 1], ah[0], bh[2], bh[3]);
            mma16(c[1][2 * g],     ah[1], bh[0], bh[1]);
            mma16(c[1][2 * g + 1], ah[1], bh[2], bh[3]);
            mma16(c[0][2 * g],     ah[0], bl[0], bl[1]);
            mma16(c[0][2 * g + 1], ah[0], bl[2], bl[3]);
            mma16(c[1][2 * g],     ah[1], bl[0], bl[1]);
            mma16(c[1][2 * g + 1], ah[1], bl[2], bl[3]);
            mma16(c[0][2 * g],     al[0], bh[0], bh[1]);
            mma16(c[0][2 * g + 1], al[0], bh[2], bh[3]);
            mma16(c[1][2 * g],     al[1], bh[0], bh[1]);
            mma16(c[1][2 * g + 1], al[1], bh[2], bh[3]);
        }
    }
}

// ---------------------------------------------------------------------------
// GEMM1 (transposed): Kt[j,i] = mask(Z[j]==Z_ref[i]) * (desc[j].X_ref[i])^expK
// 256 threads / CTA, 8 warps, warp grid 4x2 of 32x64 tiles.  (unchanged)
// ---------------------------------------------------------------------------
__global__ __launch_bounds__(256, 2) void gemm1_mma(const int* __restrict__ Zq,
                                                    const int* __restrict__ Zx,
                                                    const int* __restrict__ expKp) {
    extern __shared__ char dynsm[];
    const int tid = threadIdx.x, lane = tid & 31, wid = tid >> 5;
    const int warpM = wid & 3, warpN = wid >> 2;
    const int jBase = blockIdx.y * 128, iBase = blockIdx.x * 128;

    int* Zcol = (int*)(dynsm + 2 * STAGE_BYTES);
    if (tid < 128) Zcol[tid] = Zx[iBase + tid];

    float c[2][8][4];
#pragma unroll
    for (int i = 0; i < 2; i++)
#pragma unroll
        for (int j = 0; j < 8; j++)
#pragma unroll
            for (int k = 0; k < 4; k++) c[i][j][k] = 0.0f;

    unsigned st[2][4];
#pragma unroll
    for (int s = 0; s < 2; s++)
#pragma unroll
        for (int t = 0; t < 4; t++)
            st[s][t] = sm32(dynsm + s * STAGE_BYTES + t * TILE_BYTES);

    load_tile(st[0][0], g_Dh, jBase, DFEAT, 0, tid);
    load_tile(st[0][1], g_Dl, jBase, DFEAT, 0, tid);
    load_tile(st[0][2], g_Xh, iBase, DFEAT, 0, tid);
    load_tile(st[0][3], g_Xl, iBase, DFEAT, 0, tid);
    asm volatile("cp.async.commit_group;" ::: "memory");

    const int NITER = DFEAT / 32;       // 16
    for (int it = 0; it < NITER; it++) {
        const int b = it & 1;
        if (it + 1 < NITER) {
            const int kOff = (it + 1) * 32;
            load_tile(st[1 - b][0], g_Dh, jBase, DFEAT, kOff, tid);
            load_tile(st[1 - b][1], g_Dl, jBase, DFEAT, kOff, tid);
            load_tile(st[1 - b][2], g_Xh, iBase, DFEAT, kOff, tid);
            load_tile(st[1 - b][3], g_Xl, iBase, DFEAT, kOff, tid);
            asm volatile("cp.async.commit_group;" ::: "memory");
            asm volatile("cp.async.wait_group 1;" ::: "memory");
        } else {
            asm volatile("cp.async.wait_group 0;" ::: "memory");
        }
        __syncthreads();
        compute3_k32(st[b][0], st[b][1], st[b][2], st[b][3], warpM, warpN, lane, c);
        __syncthreads();
    }

    // epilogue: pow, mask, bf16 hi/lo split, store K^T
    const int e = expKp[0];
#pragma unroll
    for (int mi = 0; mi < 2; mi++) {
        const int r0 = jBase + warpM * 32 + mi * 16 + (lane >> 2);
        const int zr0 = Zq[r0], zr1 = Zq[r0 + 8];
        const size_t ro0 = (size_t)r0 * NREF, ro1 = (size_t)(r0 + 8) * NREF;
#pragma unroll
        for (int ni = 0; ni < 8; ni++) {
            const int colL = warpN * 64 + ni * 8 + 2 * (lane & 3);
            const int zc0 = Zcol[colL], zc1 = Zcol[colL + 1];
            float v0 = c[mi][ni][0], v1 = c[mi][ni][1];
            float v2 = c[mi][ni][2], v3 = c[mi][ni][3];
            float p0 = 1.f, p1 = 1.f, p2 = 1.f, p3 = 1.f;
            for (int t = 0; t < e; t++) { p0 *= v0; p1 *= v1; p2 *= v2; p3 *= v3; }
            if (zr0 != zc0) p0 = 0.f;
            if (zr0 != zc1) p1 = 0.f;
            if (zr1 != zc0) p2 = 0.f;
            if (zr1 != zc1) p3 = 0.f;

            __nv_bfloat16 h0 = __float2bfloat16(p0), h1 = __float2bfloat16(p1);
            __nv_bfloat16 h2 = __float2bfloat16(p2), h3 = __float2bfloat16(p3);
            __nv_bfloat162 hh01, hh23, ll01, ll23;
            hh01.x = h0; hh01.y = h1;
            hh23.x = h2; hh23.y = h3;
            ll01.x = __float2bfloat16(p0 - __bfloat162float(h0));
            ll01.y = __float2bfloat16(p1 - __bfloat162float(h1));
            ll23.x = __float2bfloat16(p2 - __bfloat162float(h2));
            ll23.y = __float2bfloat16(p3 - __bfloat162float(h3));

            const size_t cg = (size_t)iBase + colL;
            *(__nv_bfloat162*)(g_Kth + ro0 + cg) = hh01;
            *(__nv_bfloat162*)(g_Kth + ro1 + cg) = hh23;
            *(__nv_bfloat162*)(g_Ktl + ro0 + cg) = ll01;
            *(__nv_bfloat162*)(g_Ktl + ro1 + cg) = ll23;
        }
    }
}

// ---------------------------------------------------------------------------
// GEMM2 split-K: P[z][p,j] = Alpha[p, zK..] . Kt[j, zK..]   (128x128 tile)
// grid (64, 2, 2) = 256 CTAs -> full 2-CTA/SM wave with unchanged traffic.
// ---------------------------------------------------------------------------
__global__ __launch_bounds__(256, 2) void gemm2_mma(void) {
    extern __shared__ char dynsm[];
    const int tid = threadIdx.x, lane = tid & 31, wid = tid >> 5;
    const int warpM = wid & 3, warpN = wid >> 2;
    const int pBase = blockIdx.y * 128, jBase = blockIdx.x * 128;
    const int kBase = blockIdx.z * (NREF / 2);
    float* P = g_P + (size_t)blockIdx.z * PDIM * NIN;

    float c[2][8][4];
#pragma unroll
    for (int i = 0; i < 2; i++)
#pragma unroll
        for (int j = 0; j < 8; j++)
#pragma unroll
            for (int k = 0; k < 4; k++) c[i][j][k] = 0.0f;

    unsigned st[2][4];
#pragma unroll
    for (int s = 0; s < 2; s++)
#pragma unroll
        for (int t = 0; t < 4; t++)
            st[s][t] = sm32(dynsm + s * STAGE_BYTES + t * TILE_BYTES);

    load_tile(st[0][0], g_Ah, pBase, NREF, kBase, tid);
    load_tile(st[0][1], g_Al, pBase, NREF, kBase, tid);
    load_tile(st[0][2], g_Kth, jBase, NREF, kBase, tid);
    load_tile(st[0][3], g_Ktl, jBase, NREF, kBase, tid);
    asm volatile("cp.async.commit_group;" ::: "memory");

    const int NITER = (NREF / 2) / 32;  // 64
    for (int it = 0; it < NITER; it++) {
        const int b = it & 1;
        if (it + 1 < NITER) {
            const int kOff = kBase + (it + 1) * 32;
            load_tile(st[1 - b][0], g_Ah, pBase, NREF, kOff, tid);
            load_tile(st[1 - b][1], g_Al, pBase, NREF, kOff, tid);
            load_tile(st[1 - b][2], g_Kth, jBase, NREF, kOff, tid);
            load_tile(st[1 - b][3], g_Ktl, jBase, NREF, kOff, tid);
            asm volatile("cp.async.commit_group;" ::: "memory");
            asm volatile("cp.async.wait_group 1;" ::: "memory");
        } else {
            asm volatile("cp.async.wait_group 0;" ::: "memory");
        }
        __syncthreads();
        compute3_k32(st[b][0], st[b][1], st[b][2], st[b][3], warpM, warpN, lane, c);
        __syncthreads();
    }

#pragma unroll
    for (int mi = 0; mi < 2; mi++) {
        const int r0 = pBase + warpM * 32 + mi * 16 + (lane >> 2);
        const size_t ro0 = (size_t)r0 * NIN, ro1 = (size_t)(r0 + 8) * NIN;
#pragma unroll
        for (int ni = 0; ni < 8; ni++) {
            const int col = jBase + warpN * 64 + ni * 8 + 2 * (lane & 3);
            *(float2*)(P + ro0 + col) = make_float2(c[mi][ni][0], c[mi][ni][1]);
            *(float2*)(P + ro1 + col) = make_float2(c[mi][ni][2], c[mi][ni][3]);
        }
    }
}

// Reduce the two split-K partials into the output.
__global__ void reduceY(float* __restrict__ Y) {
    int i = blockIdx.x * blockDim.x + threadIdx.x;
    const int n4 = PDIM * NIN / 4;
    if (i < n4) {
        float4 a = ((const float4*)g_P)[i];
        float4 b = ((const float4*)(g_P + PDIM * NIN))[i];
        ((float4*)Y)[i] = make_float4(a.x + b.x, a.y + b.y, a.z + b.z, a.w + b.w);
    }
}

// ---------------------------------------------------------------------------
// fp32 -> bf16 hi/lo splits
// ---------------------------------------------------------------------------
__device__ __forceinline__ void split2(float2 v, __nv_bfloat162* hp, __nv_bfloat162* lp, int i) {
    __nv_bfloat16 h0 = __float2bfloat16(v.x), h1 = __float2bfloat16(v.y);
    __nv_bfloat162 hh, ll;
    hh.x = h0; hh.y = h1;
    ll.x = __float2bfloat16(v.x - __bfloat162float(h0));
    ll.y = __float2bfloat16(v.y - __bfloat162float(h1));
    hp[i] = hh; lp[i] = ll;
}
__global__ void split_X(const float* __restrict__ x) {
    int i = blockIdx.x * blockDim.x + threadIdx.x;
    if (i < NREF * DFEAT / 2)
        split2(((const float2*)x)[i], (__nv_bfloat162*)g_Xh, (__nv_bfloat162*)g_Xl, i);
}
__global__ void split_D(const float* __restrict__ x) {
    int i = blockIdx.x * blockDim.x + threadIdx.x;
    if (i < NIN * DFEAT / 2)
        split2(((const float2*)x)[i], (__nv_bfloat162*)g_Dh, (__nv_bfloat162*)g_Dl, i);
}
__global__ void split_A(const float* __restrict__ x) {
    int i = blockIdx.x * blockDim.x + threadIdx.x;
    if (i < PDIM * NREF / 2)
        split2(((const float2*)x)[i], (__nv_bfloat162*)g_Ah, (__nv_bfloat162*)g_Al, i);
}

extern "C" void kernel_launch(void* const* d_in, const int* in_sizes, int n_in,
                              void* d_out, int out_size) {
    const float* Alpha = (const float*)d_in[0];
    const float* X_ref = (const float*)d_in[1];
    const float* desc  = (const float*)d_in[2];
    const int*   Z_ref = (const int*)d_in[3];
    const int*   Z     = (const int*)d_in[4];
    const int*   expK  = (const int*)d_in[5];
    float* Y = (float*)d_out;

    cudaFuncSetAttribute(gemm1_mma, cudaFuncAttributeMaxDynamicSharedMemorySize, SMEM_TOTAL);
    cudaFuncSetAttribute(gemm2_mma, cudaFuncAttributeMaxDynamicSharedMemorySize, SMEM_TOTAL);

    split_X<<<(NREF * DFEAT / 2 + 255) / 256, 256>>>(X_ref);
    split_D<<<(NIN * DFEAT / 2 + 255) / 256, 256>>>(desc);
    split_A<<<(PDIM * NREF / 2 + 255) / 256, 256>>>(Alpha);

    gemm1_mma<<<dim3(NREF / 128, NIN / 128), 256, SMEM_TOTAL>>>(Z, Z_ref, expK);
    gemm2_mma<<<dim3(NIN / 128, PDIM / 128, 2), 256, SMEM_TOTAL>>>();
    reduceY<<<(PDIM * NIN / 4 + 255) / 256, 256>>>(Y);
}

// round 9
// speedup vs baseline: 1.1259x; 1.0641x over previous
#include <cuda_runtime.h>
#include <cuda_bf16.h>

#define NREF  4096
#define NIN   8192
#define DFEAT 512
#define PDIM  256

// Swizzled tile: 128 rows x 32 bf16 = 64B/row, no padding.
// chunk' = chunk ^ ((row>>1)&3): conflict-free for cp.async 16B stores and
// ldmatrix 8-lane phases.
#define TILE_B   8192                       // 128*64
#define STAGE_B  (4 * TILE_B)               // 32768: Ah, Al, Bh, Bl
#define NSTAGE   3
#define SMEM_TOTAL (NSTAGE * STAGE_B + 512) // 98816

// ---------------- scratch (device globals: allocation-guard safe) ----------
__device__ __nv_bfloat16 g_Xh[NREF * DFEAT];
__device__ __nv_bfloat16 g_Xl[NREF * DFEAT];
__device__ __nv_bfloat16 g_Dh[NIN * DFEAT];
__device__ __nv_bfloat16 g_Dl[NIN * DFEAT];
__device__ __nv_bfloat16 g_Ah[PDIM * NREF];
__device__ __nv_bfloat16 g_Al[PDIM * NREF];
__device__ __nv_bfloat16 g_Kth[(size_t)NIN * NREF];   // K^T hi  [NIN, NREF]
__device__ __nv_bfloat16 g_Ktl[(size_t)NIN * NREF];   // K^T lo
__device__ float g_P[2 * PDIM * NIN];                 // split-K partials (16 MB)

__device__ __forceinline__ unsigned sm32(const void* p) {
    unsigned r;
    asm("{.reg .u64 t; cvta.to.shared.u64 t, %1; cvt.u32.u64 %0, t;}" : "=r"(r) : "l"(p));
    return r;
}

// Load one 128x32 bf16 tile into swizzled smem. 256 threads, 2 chunks each.
__device__ __forceinline__ void load_tile(unsigned sbuf, const __nv_bfloat16* src,
                                          int rowBase, int K, int kOff, int tid) {
    const int row = tid >> 1;
    const int ch0 = (tid & 1) * 2;
    const char* g = (const char*)(src + (size_t)(rowBase + row) * K + kOff) + ch0 * 16;
    const int sw = (row >> 1) & 3;
    const unsigned s0 = sbuf + row * 64 + (((ch0)     ^ sw) << 4);
    const unsigned s1 = sbuf + row * 64 + (((ch0 + 1) ^ sw) << 4);
    asm volatile("cp.async.cg.shared.global [%0], [%1], 16;\n\t"
                 "cp.async.cg.shared.global [%2], [%3], 16;"
                 :: "r"(s0), "l"(g), "r"(s1), "l"(g + 16));
}

__device__ __forceinline__ void mma16(float* c, const unsigned* a, unsigned b0, unsigned b1) {
    asm volatile(
        "mma.sync.aligned.m16n8k16.row.col.f32.bf16.bf16.f32 "
        "{%0,%1,%2,%3}, {%4,%5,%6,%7}, {%8,%9}, {%0,%1,%2,%3};"
        : "+f"(c[0]), "+f"(c[1]), "+f"(c[2]), "+f"(c[3])
        : "r"(a[0]), "r"(a[1]), "r"(a[2]), "r"(a[3]), "r"(b0), "r"(b1));
}

#define LDSM4(r, addr)                                                           \
    asm volatile("ldmatrix.sync.aligned.m8n8.x4.shared.b16 {%0,%1,%2,%3}, [%4];" \
                 : "=r"((r)[0]), "=r"((r)[1]), "=r"((r)[2]), "=r"((r)[3])        \
                 : "r"(addr))

__device__ __forceinline__ unsigned sw_addr(unsigned base, int row, int ch) {
    return base + row * 64 + ((ch ^ ((row >> 1) & 3)) << 4);
}

// One BLK_K=32 stage (32x64 warp tile), fused 3-term split accumulation:
//   c += Ah.Bh + Ah.Bl + Al.Bh  (terms outermost: accumulator reuse distance 4)
__device__ __forceinline__ void compute3_k32(unsigned sAh, unsigned sAl,
                                             unsigned sBh, unsigned sBl,
                                             int warpM, int warpN, int lane,
                                             float (*c)[8][4]) {
#pragma unroll
    for (int kk = 0; kk < 32; kk += 16) {
        unsigned ah[2][4], al[2][4];
#pragma unroll
        for (int mi = 0; mi < 2; mi++) {
            const int r  = warpM * 32 + mi * 16 + (lane & 15);
            const int ch = (kk >> 3) + ((lane >> 4) & 1);
            const unsigned off = sw_addr(0, r, ch);
            LDSM4(ah[mi], sAh + off);
            LDSM4(al[mi], sAl + off);
        }
#pragma unroll
        for (int g = 0; g < 4; g++) {
            const int rb  = warpN * 64 + g * 16 + (lane & 7) + ((lane >> 4) & 1) * 8;
            const int chb = (kk >> 3) + ((lane >> 3) & 1);
            const unsigned boff = sw_addr(0, rb, chb);
            unsigned bh[4], bl[4];
            LDSM4(bh, sBh + boff);
            LDSM4(bl, sBl + boff);
            mma16(c[0][2 * g],     ah[0], bh[0], bh[1]);
            mma16(c[0][2 * g + 1], ah[0], bh[2], bh[3]);
            mma16(c[1][2 * g],     ah[1], bh[0], bh[1]);
            mma16(c[1][2 * g + 1], ah[1], bh[2], bh[3]);
            mma16(c[0][2 * g],     ah[0], bl[0], bl[1]);
            mma16(c[0][2 * g + 1], ah[0], bl[2], bl[3]);
            mma16(c[1][2 * g],     ah[1], bl[0], bl[1]);
            mma16(c[1][2 * g + 1], ah[1], bl[2], bl[3]);
            mma16(c[0][2 * g],     al[0], bh[0], bh[1]);
            mma16(c[0][2 * g + 1], al[0], bh[2], bh[3]);
            mma16(c[1][2 * g],     al[1], bh[0], bh[1]);
            mma16(c[1][2 * g + 1], al[1], bh[2], bh[3]);
        }
    }
}

// ---------------------------------------------------------------------------
// GEMM1 (transposed): Kt[j,i] = mask(Z[j]==Z_ref[i]) * (desc[j].X_ref[i])^expK
// 3-stage cp.async pipeline, ONE __syncthreads per K32 iteration.
// ---------------------------------------------------------------------------
__global__ __launch_bounds__(256, 2) void gemm1_mma(const int* __restrict__ Zq,
                                                    const int* __restrict__ Zx,
                                                    const int* __restrict__ expKp) {
    extern __shared__ char dynsm[];
    const int tid = threadIdx.x, lane = tid & 31, wid = tid >> 5;
    const int warpM = wid & 3, warpN = wid >> 2;
    const int jBase = blockIdx.y * 128, iBase = blockIdx.x * 128;

    int* Zcol = (int*)(dynsm + NSTAGE * STAGE_B);
    if (tid < 128) Zcol[tid] = Zx[iBase + tid];

    float c[2][8][4];
#pragma unroll
    for (int i = 0; i < 2; i++)
#pragma unroll
        for (int j = 0; j < 8; j++)
#pragma unroll
            for (int k = 0; k < 4; k++) c[i][j][k] = 0.0f;

    unsigned st[NSTAGE][4];
#pragma unroll
    for (int s = 0; s < NSTAGE; s++)
#pragma unroll
        for (int t = 0; t < 4; t++)
            st[s][t] = sm32(dynsm + s * STAGE_B + t * TILE_B);

    // prologue: stages 0,1
#pragma unroll
    for (int s = 0; s < 2; s++) {
        load_tile(st[s][0], g_Dh, jBase, DFEAT, s * 32, tid);
        load_tile(st[s][1], g_Dl, jBase, DFEAT, s * 32, tid);
        load_tile(st[s][2], g_Xh, iBase, DFEAT, s * 32, tid);
        load_tile(st[s][3], g_Xl, iBase, DFEAT, s * 32, tid);
        asm volatile("cp.async.commit_group;" ::: "memory");
    }

    const int NITER = DFEAT / 32;       // 16
    for (int it = 0; it < NITER; it++) {
        asm volatile("cp.async.wait_group 1;" ::: "memory");
        __syncthreads();
        if (it + 2 < NITER) {
            const int s = (it + 2) % NSTAGE, kOff = (it + 2) * 32;
            load_tile(st[s][0], g_Dh, jBase, DFEAT, kOff, tid);
            load_tile(st[s][1], g_Dl, jBase, DFEAT, kOff, tid);
            load_tile(st[s][2], g_Xh, iBase, DFEAT, kOff, tid);
            load_tile(st[s][3], g_Xl, iBase, DFEAT, kOff, tid);
        }
        asm volatile("cp.async.commit_group;" ::: "memory");
        const int b = it % NSTAGE;
        compute3_k32(st[b][0], st[b][1], st[b][2], st[b][3], warpM, warpN, lane, c);
    }

    // epilogue: pow, mask, bf16 hi/lo split, store K^T
    const int e = expKp[0];
#pragma unroll
    for (int mi = 0; mi < 2; mi++) {
        const int r0 = jBase + warpM * 32 + mi * 16 + (lane >> 2);
        const int zr0 = Zq[r0], zr1 = Zq[r0 + 8];
        const size_t ro0 = (size_t)r0 * NREF, ro1 = (size_t)(r0 + 8) * NREF;
#pragma unroll
        for (int ni = 0; ni < 8; ni++) {
            const int colL = warpN * 64 + ni * 8 + 2 * (lane & 3);
            const int zc0 = Zcol[colL], zc1 = Zcol[colL + 1];
            float v0 = c[mi][ni][0], v1 = c[mi][ni][1];
            float v2 = c[mi][ni][2], v3 = c[mi][ni][3];
            float p0 = 1.f, p1 = 1.f, p2 = 1.f, p3 = 1.f;
            for (int t = 0; t < e; t++) { p0 *= v0; p1 *= v1; p2 *= v2; p3 *= v3; }
            if (zr0 != zc0) p0 = 0.f;
            if (zr0 != zc1) p1 = 0.f;
            if (zr1 != zc0) p2 = 0.f;
            if (zr1 != zc1) p3 = 0.f;

            __nv_bfloat16 h0 = __float2bfloat16(p0), h1 = __float2bfloat16(p1);
            __nv_bfloat16 h2 = __float2bfloat16(p2), h3 = __float2bfloat16(p3);
            __nv_bfloat162 hh01, hh23, ll01, ll23;
            hh01.x = h0; hh01.y = h1;
            hh23.x = h2; hh23.y = h3;
            ll01.x = __float2bfloat16(p0 - __bfloat162float(h0));
            ll01.y = __float2bfloat16(p1 - __bfloat162float(h1));
            ll23.x = __float2bfloat16(p2 - __bfloat162float(h2));
            ll23.y = __float2bfloat16(p3 - __bfloat162float(h3));

            const size_t cg = (size_t)iBase + colL;
            *(__nv_bfloat162*)(g_Kth + ro0 + cg) = hh01;
            *(__nv_bfloat162*)(g_Kth + ro1 + cg) = hh23;
            *(__nv_bfloat162*)(g_Ktl + ro0 + cg) = ll01;
            *(__nv_bfloat162*)(g_Ktl + ro1 + cg) = ll23;
        }
    }
}

// ---------------------------------------------------------------------------
// GEMM2 split-K: P[z][p,j] = Alpha[p, zK..] . Kt[j, zK..]   (128x128 tile)
// grid (64, 2, 2) = 256 CTAs, 3-stage pipeline, one barrier per iteration.
// ---------------------------------------------------------------------------
__global__ __launch_bounds__(256, 2) void gemm2_mma(void) {
    extern __shared__ char dynsm[];
    const int tid = threadIdx.x, lane = tid & 31, wid = tid >> 5;
    const int warpM = wid & 3, warpN = wid >> 2;
    const int pBase = blockIdx.y * 128, jBase = blockIdx.x * 128;
    const int kBase = blockIdx.z * (NREF / 2);
    float* P = g_P + (size_t)blockIdx.z * PDIM * NIN;

    float c[2][8][4];
#pragma unroll
    for (int i = 0; i < 2; i++)
#pragma unroll
        for (int j = 0; j < 8; j++)
#pragma unroll
            for (int k = 0; k < 4; k++) c[i][j][k] = 0.0f;

    unsigned st[NSTAGE][4];
#pragma unroll
    for (int s = 0; s < NSTAGE; s++)
#pragma unroll
        for (int t = 0; t < 4; t++)
            st[s][t] = sm32(dynsm + s * STAGE_B + t * TILE_B);

#pragma unroll
    for (int s = 0; s < 2; s++) {
        const int kOff = kBase + s * 32;
        load_tile(st[s][0], g_Ah, pBase, NREF, kOff, tid);
        load_tile(st[s][1], g_Al, pBase, NREF, kOff, tid);
        load_tile(st[s][2], g_Kth, jBase, NREF, kOff, tid);
        load_tile(st[s][3], g_Ktl, jBase, NREF, kOff, tid);
        asm volatile("cp.async.commit_group;" ::: "memory");
    }

    const int NITER = (NREF / 2) / 32;  // 64
    for (int it = 0; it < NITER; it++) {
        asm volatile("cp.async.wait_group 1;" ::: "memory");
        __syncthreads();
        if (it + 2 < NITER) {
            const int s = (it + 2) % NSTAGE, kOff = kBase + (it + 2) * 32;
            load_tile(st[s][0], g_Ah, pBase, NREF, kOff, tid);
            load_tile(st[s][1], g_Al, pBase, NREF, kOff, tid);
            load_tile(st[s][2], g_Kth, jBase, NREF, kOff, tid);
            load_tile(st[s][3], g_Ktl, jBase, NREF, kOff, tid);
        }
        asm volatile("cp.async.commit_group;" ::: "memory");
        const int b = it % NSTAGE;
        compute3_k32(st[b][0], st[b][1], st[b][2], st[b][3], warpM, warpN, lane, c);
    }

#pragma unroll
    for (int mi = 0; mi < 2; mi++) {
        const int r0 = pBase + warpM * 32 + mi * 16 + (lane >> 2);
        const size_t ro0 = (size_t)r0 * NIN, ro1 = (size_t)(r0 + 8) * NIN;
#pragma unroll
        for (int ni = 0; ni < 8; ni++) {
            const int col = jBase + warpN * 64 + ni * 8 + 2 * (lane & 3);
            *(float2*)(P + ro0 + col) = make_float2(c[mi][ni][0], c[mi][ni][1]);
            *(float2*)(P + ro1 + col) = make_float2(c[mi][ni][2], c[mi][ni][3]);
        }
    }
}

// Reduce the two split-K partials into the output.
__global__ void reduceY(float* __restrict__ Y) {
    int i = blockIdx.x * blockDim.x + threadIdx.x;
    const int n4 = PDIM * NIN / 4;
    if (i < n4) {
        float4 a = ((const float4*)g_P)[i];
        float4 b = ((const float4*)(g_P + PDIM * NIN))[i];
        ((float4*)Y)[i] = make_float4(a.x + b.x, a.y + b.y, a.z + b.z, a.w + b.w);
    }
}

// ---------------------------------------------------------------------------
// fp32 -> bf16 hi/lo splits
// ---------------------------------------------------------------------------
__device__ __forceinline__ void split2(float2 v, __nv_bfloat162* hp, __nv_bfloat162* lp, int i) {
    __nv_bfloat16 h0 = __float2bfloat16(v.x), h1 = __float2bfloat16(v.y);
    __nv_bfloat162 hh, ll;
    hh.x = h0; hh.y = h1;
    ll.x = __float2bfloat16(v.x - __bfloat162float(h0));
    ll.y = __float2bfloat16(v.y - __bfloat162float(h1));
    hp[i] = hh; lp[i] = ll;
}
__global__ void split_X(const float* __restrict__ x) {
    int i = blockIdx.x * blockDim.x + threadIdx.x;
    if (i < NREF * DFEAT / 2)
        split2(((const float2*)x)[i], (__nv_bfloat162*)g_Xh, (__nv_bfloat162*)g_Xl, i);
}
__global__ void split_D(const float* __restrict__ x) {
    int i = blockIdx.x * blockDim.x + threadIdx.x;
    if (i < NIN * DFEAT / 2)
        split2(((const float2*)x)[i], (__nv_bfloat162*)g_Dh, (__nv_bfloat162*)g_Dl, i);
}
__global__ void split_A(const float* __restrict__ x) {
    int i = blockIdx.x * blockDim.x + threadIdx.x;
    if (i < PDIM * NREF / 2)
        split2(((const float2*)x)[i], (__nv_bfloat162*)g_Ah, (__nv_bfloat162*)g_Al, i);
}

extern "C" void kernel_launch(void* const* d_in, const int* in_sizes, int n_in,
                              void* d_out, int out_size) {
    const float* Alpha = (const float*)d_in[0];
    const float* X_ref = (const float*)d_in[1];
    const float* desc  = (const float*)d_in[2];
    const int*   Z_ref = (const int*)d_in[3];
    const int*   Z     = (const int*)d_in[4];
    const int*   expK  = (const int*)d_in[5];
    float* Y = (float*)d_out;

    cudaFuncSetAttribute(gemm1_mma, cudaFuncAttributeMaxDynamicSharedMemorySize, SMEM_TOTAL);
    cudaFuncSetAttribute(gemm2_mma, cudaFuncAttributeMaxDynamicSharedMemorySize, SMEM_TOTAL);

    split_X<<<(NREF * DFEAT / 2 + 255) / 256, 256>>>(X_ref);
    split_D<<<(NIN * DFEAT / 2 + 255) / 256, 256>>>(desc);
    split_A<<<(PDIM * NREF / 2 + 255) / 256, 256>>>(Alpha);

    gemm1_mma<<<dim3(NREF / 128, NIN / 128), 256, SMEM_TOTAL>>>(Z, Z_ref, expK);
    gemm2_mma<<<dim3(NIN / 128, PDIM / 128, 2), 256, SMEM_TOTAL>>>();
    reduceY<<<(PDIM * NIN / 4 + 255) / 256, 256>>>(Y);
}